// round 12
// baseline (speedup 1.0000x reference)
#include <cuda_runtime.h>

// VectorQuantize, register-tiled fp32. B x 64 rows vs 512 x 64 codebook.
// R12 = R11 (8x8 tile, 256 thr, 255-reg budget) + manual double-buffered
// dp pipeline (R8 structure, which failed ONLY due to the 128-reg cap).
// R11 profile showed fma 57% + L1 55% = alternating phases; overlapping
// loads of dp+1 with FMA of dp targets the 252us dual-pipe roofline.
//
// Precision contract (validated R1/R3/R4/R7-R11, rel_err == 0.0): fp32
// throughout, dist = fl(fl(z_sq - 2*dot) + c_sq); dot = single f32x2 chain
// over dp ascending then fl(x+y); z_sq 4-chain stride-4; c_sq sequential
// scalar; argmin strict '<' ascending k in-thread, lexicographic (dist,k)
// across threads -> first-index tie break (jnp.argmin).

#define VQ_K     512
#define VQ_D     64
#define VQ_TPB   256
#define VQ_MT    256        // rows per CTA
#define VQ_RT    8          // rows per thread (4 pairs strided by 64)
#define VQ_KT    8          // codes per thread per sweep
#define VQ_SC    512        // cT2 dp-row stride (ull)
#define VQ_SZ    256        // zT2 dp-row stride (ull)
#define VQ_NIT   8          // k-sweeps (64 codes per sweep)
#define VQ_RED   9          // reduction row stride (8 tx + 1 pad)

typedef unsigned long long ull;

__device__ __forceinline__ ull vq_fma2(ull a, ull b, ull c) {
    ull d;
    asm("fma.rn.f32x2 %0, %1, %2, %3;" : "=l"(d) : "l"(a), "l"(b), "l"(c));
    return d;
}
__device__ __forceinline__ ull vq_add2(ull a, ull b) {
    ull d;
    asm("add.rn.f32x2 %0, %1, %2;" : "=l"(d) : "l"(a), "l"(b));
    return d;
}
__device__ __forceinline__ float2 vq_unpack(ull a) {
    float2 f;
    asm("mov.b64 {%0, %1}, %2;" : "=f"(f.x), "=f"(f.y) : "l"(a));
    return f;
}
__device__ __forceinline__ ull vq_pack(float x, float y) {
    ull d;
    asm("mov.b64 %0, {%1, %2};" : "=l"(d) : "f"(x), "f"(y));
    return d;
}

#define VQ_CT2_ULL (32 * VQ_SC)      // 16384 ull = 131072 B
#define VQ_ZT2_ULL (32 * VQ_SZ)      //  8192 ull =  65536 B
#define VQ_SMEM_BYTES ((VQ_CT2_ULL + VQ_ZT2_ULL) * 8 + (VQ_K + VQ_MT) * 4)
// reduction overlay on zT2: 256*9*(4+4) = 18432 B < 65536 B

__global__ void __launch_bounds__(VQ_TPB, 1)
vq_kernel(const float* __restrict__ z, const float* __restrict__ cb,
          float* __restrict__ out, int B) {
    extern __shared__ ull sm[];
    ull*   cT2   = sm;                           // [dp*512 + k]
    ull*   zT2   = sm + VQ_CT2_ULL;              // [dp*256 + r]
    float* s_csq = (float*)(zT2 + VQ_ZT2_ULL);   // [512]
    float* s_zsq = s_csq + VQ_K;                 // [256]
    float* s_rd  = (float*)zT2;                  // overlay [256*9]
    int*   s_rk  = (int*)(s_rd + VQ_MT * VQ_RED);// overlay [256*9]

    const int tid = threadIdx.x;
    const long long base = (long long)blockIdx.x * VQ_MT;
    const int rows_in = (int)((B - base) < VQ_MT ? (B - base) : VQ_MT);

    // ---- stage codebook transposed, k-minor (conflict-free STS) ----
    {
        const float4* cb4 = reinterpret_cast<const float4*>(cb);
        #pragma unroll 4
        for (int i = tid; i < VQ_K * 16; i += VQ_TPB) {
            int k = i & 511, dg = i >> 9;
            float4 v = cb4[k * 16 + dg];
            cT2[(2 * dg)     * VQ_SC + k] = vq_pack(v.x, v.y);
            cT2[(2 * dg + 1) * VQ_SC + k] = vq_pack(v.z, v.w);
        }
    }
    // ---- stage z tile transposed, r-minor (conflict-free STS) ----
    {
        const float4* z4 = reinterpret_cast<const float4*>(z + base * VQ_D);
        #pragma unroll 4
        for (int i = tid; i < VQ_MT * 16; i += VQ_TPB) {
            int r = i & 255, dg = i >> 8;
            float4 v = (r < rows_in) ? z4[r * 16 + dg]
                                     : make_float4(0.f, 0.f, 0.f, 0.f);
            zT2[(2 * dg)     * VQ_SZ + r] = vq_pack(v.x, v.y);
            zT2[(2 * dg + 1) * VQ_SZ + r] = vq_pack(v.z, v.w);
        }
    }
    __syncthreads();

    // ---- c_sq: sequential scalar over d ascending (chain == R1..R11) ----
    #pragma unroll
    for (int k = tid; k < VQ_K; k += VQ_TPB) {
        float s = 0.0f;
        #pragma unroll
        for (int dp = 0; dp < 32; ++dp) {
            float2 c = vq_unpack(cT2[dp * VQ_SC + k]);
            s = __fmaf_rn(c.x, c.x, s);
            s = __fmaf_rn(c.y, c.y, s);
        }
        s_csq[k] = s;
    }
    // ---- z_sq: 4-chain pairwise, stride-4 interleave (chain == R1..R11) ----
    {
        int r = tid;   // TPB == 256 == VQ_MT
        ull a0 = 0, a1 = 0, a2 = 0, a3 = 0;
        #pragma unroll
        for (int i = 0; i < 32; i += 4) {
            ull p0 = zT2[(i + 0) * VQ_SZ + r];
            ull p1 = zT2[(i + 1) * VQ_SZ + r];
            ull p2 = zT2[(i + 2) * VQ_SZ + r];
            ull p3 = zT2[(i + 3) * VQ_SZ + r];
            a0 = vq_fma2(p0, p0, a0);
            a1 = vq_fma2(p1, p1, a1);
            a2 = vq_fma2(p2, p2, a2);
            a3 = vq_fma2(p3, p3, a3);
        }
        float2 s = vq_unpack(vq_add2(vq_add2(a0, a1), vq_add2(a2, a3)));
        s_zsq[r] = __fadd_rn(s.x, s.y);
    }
    __syncthreads();

    // ---- main loop: 8 k-sweeps, thread tile 8 rows x 8 codes,
    //      manual double-buffered dp pipeline ----
    const int tx = tid & 7, ty = tid >> 3;       // tx [0,8), ty [0,32)
    const int r0 = 2 * ty;                       // row pairs r0+{0,1}+64p

    float best[VQ_RT];
    int   bk[VQ_RT];
    #pragma unroll
    for (int r = 0; r < VQ_RT; ++r) { best[r] = __int_as_float(0x7f800000); bk[r] = 0; }

    #pragma unroll 1
    for (int it = 0; it < VQ_NIT; ++it) {
        const int K0 = it * 64;
        const int kA = K0 + 2 * tx;   // codes kA+16i, kA+16i+1, i=0..3

        ull acc[VQ_RT][VQ_KT];
        #pragma unroll
        for (int r = 0; r < VQ_RT; ++r)
            #pragma unroll
            for (int kk = 0; kk < VQ_KT; ++kk) acc[r][kk] = 0;

        const ull* cp = cT2 + kA;
        const ull* zp = zT2 + r0;

        // prefetch dp = 0 (buffer A)
        ulonglong2 cA0 = *reinterpret_cast<const ulonglong2*>(cp);
        ulonglong2 cA1 = *reinterpret_cast<const ulonglong2*>(cp + 16);
        ulonglong2 cA2 = *reinterpret_cast<const ulonglong2*>(cp + 32);
        ulonglong2 cA3 = *reinterpret_cast<const ulonglong2*>(cp + 48);
        ulonglong2 zA0 = *reinterpret_cast<const ulonglong2*>(zp);
        ulonglong2 zA1 = *reinterpret_cast<const ulonglong2*>(zp + 64);
        ulonglong2 zA2 = *reinterpret_cast<const ulonglong2*>(zp + 128);
        ulonglong2 zA3 = *reinterpret_cast<const ulonglong2*>(zp + 192);

        #pragma unroll 2
        for (int dp = 0; dp < 32; dp += 2) {
            // prefetch dp+1 (buffer B)
            const ull* cq = cp + (dp + 1) * VQ_SC;
            const ull* zq = zp + (dp + 1) * VQ_SZ;
            ulonglong2 cB0 = *reinterpret_cast<const ulonglong2*>(cq);
            ulonglong2 cB1 = *reinterpret_cast<const ulonglong2*>(cq + 16);
            ulonglong2 cB2 = *reinterpret_cast<const ulonglong2*>(cq + 32);
            ulonglong2 cB3 = *reinterpret_cast<const ulonglong2*>(cq + 48);
            ulonglong2 zB0 = *reinterpret_cast<const ulonglong2*>(zq);
            ulonglong2 zB1 = *reinterpret_cast<const ulonglong2*>(zq + 64);
            ulonglong2 zB2 = *reinterpret_cast<const ulonglong2*>(zq + 128);
            ulonglong2 zB3 = *reinterpret_cast<const ulonglong2*>(zq + 192);

            // FMA block for dp (buffer A)
            {
                ull cf[VQ_KT] = { cA0.x, cA0.y, cA1.x, cA1.y,
                                  cA2.x, cA2.y, cA3.x, cA3.y };
                ull zr[VQ_RT] = { zA0.x, zA0.y, zA1.x, zA1.y,
                                  zA2.x, zA2.y, zA3.x, zA3.y };
                #pragma unroll
                for (int r = 0; r < VQ_RT; ++r)
                    #pragma unroll
                    for (int kk = 0; kk < VQ_KT; ++kk)
                        acc[r][kk] = vq_fma2(zr[r], cf[kk], acc[r][kk]);
            }

            // prefetch dp+2 (buffer A); guard removed by unroll (dp+2<32)
            if (dp + 2 < 32) {
                const ull* cr = cp + (dp + 2) * VQ_SC;
                const ull* zr2 = zp + (dp + 2) * VQ_SZ;
                cA0 = *reinterpret_cast<const ulonglong2*>(cr);
                cA1 = *reinterpret_cast<const ulonglong2*>(cr + 16);
                cA2 = *reinterpret_cast<const ulonglong2*>(cr + 32);
                cA3 = *reinterpret_cast<const ulonglong2*>(cr + 48);
                zA0 = *reinterpret_cast<const ulonglong2*>(zr2);
                zA1 = *reinterpret_cast<const ulonglong2*>(zr2 + 64);
                zA2 = *reinterpret_cast<const ulonglong2*>(zr2 + 128);
                zA3 = *reinterpret_cast<const ulonglong2*>(zr2 + 192);
            }

            // FMA block for dp+1 (buffer B)
            {
                ull cf[VQ_KT] = { cB0.x, cB0.y, cB1.x, cB1.y,
                                  cB2.x, cB2.y, cB3.x, cB3.y };
                ull zr[VQ_RT] = { zB0.x, zB0.y, zB1.x, zB1.y,
                                  zB2.x, zB2.y, zB3.x, zB3.y };
                #pragma unroll
                for (int r = 0; r < VQ_RT; ++r)
                    #pragma unroll
                    for (int kk = 0; kk < VQ_KT; ++kk)
                        acc[r][kk] = vq_fma2(zr[r], cf[kk], acc[r][kk]);
            }
        }

        // per-sweep epilogue: dist + argmin
        // thread codes ascending: kA+16i+{0,1} (2tx+1 < 16 -> ascending in kk)
        #pragma unroll
        for (int p = 0; p < 4; ++p) {
            #pragma unroll
            for (int h = 0; h < 2; ++h) {
                const int r = 2 * p + h;
                const float zq = s_zsq[r0 + 64 * p + h];
                #pragma unroll
                for (int kk = 0; kk < VQ_KT; ++kk) {
                    const int kc = kA + 16 * (kk >> 1) + (kk & 1);
                    float2 f = vq_unpack(acc[r][kk]);
                    float dot  = __fadd_rn(f.x, f.y);
                    float t    = __fsub_rn(zq, __fmul_rn(2.0f, dot));
                    float dist = __fadd_rn(t, s_csq[kc]);
                    bool pr = dist < best[r];
                    best[r] = pr ? dist : best[r];
                    bk[r]   = pr ? kc : bk[r];
                }
            }
        }
    }

    // ---- cross-thread argmin reduction (overlay on dead zT2) ----
    __syncthreads();   // all main-loop zT2 reads complete
    #pragma unroll
    for (int p = 0; p < 4; ++p)
        #pragma unroll
        for (int h = 0; h < 2; ++h) {
            const int row = r0 + 64 * p + h;
            s_rd[row * VQ_RED + tx] = best[2 * p + h];
            s_rk[row * VQ_RED + tx] = bk[2 * p + h];
        }
    __syncthreads();
    {
        int r = tid;   // TPB == VQ_MT
        float bd = s_rd[r * VQ_RED + 0];
        int   bi = s_rk[r * VQ_RED + 0];
        #pragma unroll
        for (int t = 1; t < 8; ++t) {
            float d = s_rd[r * VQ_RED + t];
            int   i = s_rk[r * VQ_RED + t];
            bool p = (d < bd) || (d == bd && i < bi);
            bd = p ? d : bd;
            bi = p ? i : bi;
        }
        s_rk[r * VQ_RED] = bi;
    }
    __syncthreads();

    // ---- outputs: z and cb from GLOBAL (coalesced; L2-resident) ----
    {
        const float4* cb4 = reinterpret_cast<const float4*>(cb);
        const float4* z4  = reinterpret_cast<const float4*>(z + base * VQ_D);
        float4* o1 = reinterpret_cast<float4*>(out) + base * 16;
        float4* o2 = reinterpret_cast<float4*>(out) + (long long)B * 16 + base * 16;
        #pragma unroll 4
        for (int c = tid; c < VQ_MT * 16; c += VQ_TPB) {
            int r = c >> 4, dg = c & 15;
            if (r >= rows_in) break;
            int kbest = s_rk[r * VQ_RED];
            float4 qv = cb4[kbest * 16 + dg];
            float4 zv = z4[c];
            float4 w;
            w.x = __fadd_rn(zv.x, __fsub_rn(qv.x, zv.x));
            w.y = __fadd_rn(zv.y, __fsub_rn(qv.y, zv.y));
            w.z = __fadd_rn(zv.z, __fsub_rn(qv.z, zv.z));
            w.w = __fadd_rn(zv.w, __fsub_rn(qv.w, zv.w));
            o1[c] = w;
            o2[c] = qv;
        }
    }
}

extern "C" void kernel_launch(void* const* d_in, const int* in_sizes, int n_in,
                              void* d_out, int out_size) {
    const float* z  = (const float*)d_in[0];
    const float* cb = (const float*)d_in[1];
    int sz0 = in_sizes[0];
    int sz1 = (n_in > 1) ? in_sizes[1] : 0;
    if (sz0 < sz1) {   // codebook is the small input (K*D = 32768)
        const float* t = z; z = cb; cb = t;
        int ts = sz0; sz0 = sz1; sz1 = ts;
    }
    int B = sz0 / VQ_D;

    cudaFuncSetAttribute(vq_kernel, cudaFuncAttributeMaxDynamicSharedMemorySize,
                         VQ_SMEM_BYTES);
    int grid = (B + VQ_MT - 1) / VQ_MT;
    vq_kernel<<<grid, VQ_TPB, VQ_SMEM_BYTES>>>(z, cb, (float*)d_out, B);
}